// round 17
// baseline (speedup 1.0000x reference)
#include <cuda_runtime.h>
#include <cuda_fp16.h>
#include <math.h>
#include <stdint.h>

#define NN 1024
#define BT 256  // threads for butterfly kernel

// ---------------- scratch (__device__ globals; no runtime alloc) ----------------
__device__ __half  g_Wh[NN * NN];           // 2 MB : fp16(M), [k][n]  (row k = butterfly(e_k))

// ---------------- PTX helpers (all family-agnostic: sm_80+ features) ----------------
__device__ __forceinline__ uint32_t smem_u32(const void* p) {
    uint32_t a;
    asm("{ .reg .u64 t; cvta.to.shared.u64 t, %1; cvt.u32.u64 %0, t; }" : "=r"(a) : "l"(p));
    return a;
}
#define CP_ASYNC16(s, g) \
    asm volatile("cp.async.cg.shared.global [%0], [%1], 16;" :: "r"(s), "l"(g))
#define CP_COMMIT() asm volatile("cp.async.commit_group;" ::: "memory")
#define CP_WAIT1()  asm volatile("cp.async.wait_group 1;" ::: "memory")
#define CP_WAIT0()  asm volatile("cp.async.wait_group 0;" ::: "memory")
#define LDSM4(r, addr) \
    asm volatile("ldmatrix.sync.aligned.m8n8.x4.shared.b16 {%0,%1,%2,%3}, [%4];" \
        : "=r"((r)[0]), "=r"((r)[1]), "=r"((r)[2]), "=r"((r)[3]) : "r"(addr))
#define LDSM4T(r, addr) \
    asm volatile("ldmatrix.sync.aligned.m8n8.x4.trans.shared.b16 {%0,%1,%2,%3}, [%4];" \
        : "=r"((r)[0]), "=r"((r)[1]), "=r"((r)[2]), "=r"((r)[3]) : "r"(addr))
#define MMA16816(d, a, b) \
    asm volatile("mma.sync.aligned.m16n8k16.row.col.f32.f16.f16.f32 " \
        "{%0,%1,%2,%3}, {%4,%5,%6,%7}, {%8,%9}, {%0,%1,%2,%3};" \
        : "+f"((d)[0]), "+f"((d)[1]), "+f"((d)[2]), "+f"((d)[3]) \
        : "r"((a)[0]), "r"((a)[1]), "r"((a)[2]), "r"((a)[3]), "r"((b)[0]), "r"((b)[1]))

// ================= butterfly on identity rows -> g_Wh (fp16, [k][n]) =================
// Depth-0 PERM chain only: one-hot support stays within the size-m block
// containing `row`. Diag chain restarts at m=2 AFTER the full-width m=1024
// perm mix, so it must run dense.
__global__ __launch_bounds__(BT) void butterfly_ident_kernel(
    const float* __restrict__ perm_logit, const float* __restrict__ abcd, int depth)
{
    __shared__ float2 buf[2][NN];
    const int row = blockIdx.x;
    const int t = threadIdx.x;
    // zero-init BOTH buffers (sparse perm phase relies on zeros outside blocks)
    #pragma unroll
    for (int u = 0; u < NN / BT; ++u) {
        int i = t + u * BT;
        buf[0][i] = make_float2(i == row ? 1.0f : 0.0f, 0.0f);
        buf[1][i] = make_float2(0.0f, 0.0f);
    }
    int cur = 0;
    __syncthreads();

    for (int d = 0; d < depth; ++d) {
        const float p0 = 1.0f / (1.0f + expf(-perm_logit[d * 3 + 0]));
        const float p1 = 1.0f / (1.0f + expf(-perm_logit[d * 3 + 1]));
        const float p2 = 1.0f / (1.0f + expf(-perm_logit[d * 3 + 2]));

        // ---- perm factors, m = 4..1024 (sparse for d==0) ----
        for (int m = 4; m <= NN; m <<= 1) {
            const int half = m >> 1;
            const int nxt = cur ^ 1;
            const int base = (d == 0) ? (row & ~(m - 1)) : 0;
            const int lim  = (d == 0) ? m : NN;
            for (int idx = t; idx < lim; idx += BT) {
                int i = base + idx;
                int blk = i & ~(m - 1);
                int j = i - blk;
                bool second = (j >= half);
                float pr = second ? p2 : p1;
                int sj  = second ? (2 * (j - half) + 1) : (2 * j);
                int rj  = second ? (m + half - 1 - j)   : (half - 1 - j);
                int srj = second ? (2 * (rj - half) + 1) : (2 * rj);
                float2 a  = buf[cur][blk + j];
                float2 bb = buf[cur][blk + sj];
                float2 c  = buf[cur][blk + rj];
                float2 dd = buf[cur][blk + srj];
                float ex = a.x + p0 * (bb.x - a.x);
                float ey = a.y + p0 * (bb.y - a.y);
                float fx = c.x + p0 * (dd.x - c.x);
                float fy = c.y + p0 * (dd.y - c.y);
                buf[nxt][i] = make_float2(ex + pr * (fx - ex), ey + pr * (fy - ey));
            }
            __syncthreads();
            cur = nxt;
        }

        // ---- diag factors, m = 2..1024 (ALWAYS dense) ----
        const float2* abd = (const float2*)(abcd) + (size_t)d * (4 * NN - 4);
        int lh = 0;
        for (int m = 2; m <= NN; m <<= 1, ++lh) {
            const int half = m >> 1;
            const float2* W = abd + (4 * NN - 4 * m);
            const int nxt = cur ^ 1;
            #pragma unroll
            for (int u = 0; u < (NN / 2) / BT; ++u) {
                int p  = t + u * BT;
                int bi = p >> lh;
                int k  = p & (half - 1);
                int i0 = bi * m + k;
                int i1 = i0 + half;
                float2 x0 = buf[cur][i0];
                float2 x1 = buf[cur][i1];
                float2 A  = W[k];
                float2 Bw = W[half + k];
                float2 C  = W[2 * half + k];
                float2 D  = W[3 * half + k];
                float2 y0, y1;
                y0.x = A.x * x0.x - A.y * x0.y + Bw.x * x1.x - Bw.y * x1.y;
                y0.y = A.x * x0.y + A.y * x0.x + Bw.x * x1.y + Bw.y * x1.x;
                y1.x = C.x * x0.x - C.y * x0.y + D.x * x1.x - D.y * x1.y;
                y1.y = C.x * x0.y + C.y * x0.x + D.x * x1.y + D.y * x1.x;
                buf[nxt][i0] = y0;
                buf[nxt][i1] = y1;
            }
            __syncthreads();
            cur = nxt;
        }
    }
    // write fp16 directly, [k][n] layout (coalesced)
    #pragma unroll
    for (int u = 0; u < NN / BT; ++u) {
        int i = t + u * BT;
        g_Wh[(size_t)row * NN + i] = __float2half(buf[cur][i].x);
    }
}

// ================= HMMA GEMM: out = fp16(x)*Wh + bias (conversion fused) =================
// CTA tile 128x128, K-stage 32. A: fp32 x LDG.128 prefetched 1 stage ahead ->
// cvt fp16 -> STS into 2-slot ring ([m][k], 80B stride, non-trans ldmatrix).
// B: 3-slot cp.async ring ([k][n], 272B stride, TRANS ldmatrix).
// One __syncthreads per stage (same WAR discipline as before).
#define TM 128
#define TN 128
#define TK 32
#define APADH 40                        // halves per A row
#define BPADH 136                       // halves per B row ([k][n], 128 n + pad)
#define AST (TM * APADH)                // 5120 halves
#define BSTG (TK * BPADH)               // 4352 halves
#define ASLOTS 2
#define BRING 3
#define ABYTES (AST * 2)                // 10240 B
#define BBYTES (BSTG * 2)               // 8704 B
#define SMEM_GEMM (ASLOTS * ABYTES + BRING * BBYTES)   // 46592 B
#define NSTAGES_TOT (NN / TK)           // 32

__global__ __launch_bounds__(256, 2) void gemm_kernel(
    const float* __restrict__ x, const float* __restrict__ bias, float* __restrict__ out)
{
    extern __shared__ __half smem[];
    __half* As = smem;                       // ASLOTS stages of A
    __half* Bs = smem + ASLOTS * AST;        // BRING stages of B

    const int tid = threadIdx.x;
    const int lane = tid & 31;
    const int wid = tid >> 5;
    const int wm = wid & 3;       // 4 warps over M (32 rows each)
    const int wn = wid >> 2;      // 2 warps over N (64 cols each)
    const int gn = blockIdx.x;    // N block (fast) -> A reuse in L2
    const int gm = blockIdx.y;    // M block

    float acc[2][8][4];
    #pragma unroll
    for (int mf = 0; mf < 2; ++mf)
        #pragma unroll
        for (int nf = 0; nf < 8; ++nf)
            #pragma unroll
            for (int q = 0; q < 4; ++q) acc[mf][nf][q] = 0.0f;

    const uint32_t sAbase = smem_u32(As);
    const uint32_t sBbase = smem_u32(Bs);

    // A fp32 LDG mapping: thread t -> row t>>1, 16 consecutive floats at (t&1)*16.
    const int lrow = tid >> 1;            // 0..127
    const int lkh  = (tid & 1) * 16;      // 0 or 16
    const float* xrow = x + (size_t)(gm * TM + lrow) * NN + lkh;

    // B cp.async: 32 k-rows x 256B = 512 chunks; thread t: row t>>3, chunks (t&7), (t&7)+8.
    const int br0 = tid >> 3;
    const int bc0 = tid & 7;
    const uint32_t wb0 = (uint32_t)(br0 * (BPADH * 2) + bc0 * 16);
    const uint32_t wb1 = wb0 + 128;          // chunk +8 -> +64 halves

    auto issueB = [&](int s, int slot) {
        const __half* Bp = g_Wh + (size_t)(s * TK) * NN + gn * TN;
        const uint32_t sb = sBbase + (uint32_t)(slot * BBYTES);
        CP_ASYNC16(sb + wb0, Bp + (size_t)br0 * NN + bc0 * 8);
        CP_ASYNC16(sb + wb1, Bp + (size_t)br0 * NN + bc0 * 8 + 64);
        CP_COMMIT();
    };
    auto ldgA = [&](int s, float4* r) {
        const float4* p = (const float4*)(xrow + s * TK);
        r[0] = p[0]; r[1] = p[1]; r[2] = p[2]; r[3] = p[3];
    };
    auto stsA = [&](int s, const float4* r) {
        __half* d = As + (s & 1) * AST + lrow * APADH + lkh;
        __half2 h[8];
        #pragma unroll
        for (int v = 0; v < 4; ++v) {
            h[2 * v]     = __floats2half2_rn(r[v].x, r[v].y);
            h[2 * v + 1] = __floats2half2_rn(r[v].z, r[v].w);
        }
        ((uint4*)d)[0] = *(const uint4*)(h);
        ((uint4*)(d + 8))[0] = *(const uint4*)(h + 4);
    };

    // A ldmatrix lane addressing (non-trans, [m][k])
    const int a_r = (lane & 7) | (((lane >> 3) & 1) << 3);   // m-row 0..15 within frag
    const int a_c = ((lane >> 4) & 1) * 8;                   // +8 k for mats 2,3
    const uint32_t aoff = (uint32_t)((wm * 32 + a_r) * (APADH * 2) + a_c * 2);
    // B ldmatrix lane addressing (TRANS, [k][n]): lanes supply k-rows.
    const int bk_r = (lane & 7) | (((lane >> 3) & 1) << 3);  // k-row 0..15 within frag
    const int bn_c = ((lane >> 4) & 1) * 8;                  // +8 n for mats 2,3
    const uint32_t boff = (uint32_t)(bk_r * (BPADH * 2) + (wn * 64 + bn_c) * 2);

    // prologue: 2 B stages in flight; A stage 0 in registers
    issueB(0, 0);
    issueB(1, 1);
    float4 rr[2][4];
    ldgA(0, rr[0]);

    int bslot = 0, ibslot = 2;
    #pragma unroll 2
    for (int s = 0; s < NSTAGES_TOT; ++s) {
        if (s + 1 < NSTAGES_TOT) ldgA(s + 1, rr[(s + 1) & 1]);   // prefetch next A
        stsA(s, rr[s & 1]);                                      // publish this A (slot s&1)
        if (s == NSTAGES_TOT - 1) { CP_WAIT0(); }
        else                      { CP_WAIT1(); }
        __syncthreads();   // A(s) + B(s) visible; all warps done with previous slot uses
        if (s + 2 < NSTAGES_TOT) {
            issueB(s + 2, ibslot);
            if (++ibslot == BRING) ibslot = 0;
        }
        const uint32_t sa = sAbase + (uint32_t)((s & 1) * ABYTES) + aoff;
        const uint32_t sb = sBbase + (uint32_t)(bslot * BBYTES) + boff;
        if (++bslot == BRING) bslot = 0;
        #pragma unroll
        for (int kk = 0; kk < 2; ++kk) {
            uint32_t af[2][4];
            LDSM4(af[0], sa + kk * 32);
            LDSM4(af[1], sa + kk * 32 + 16 * (APADH * 2));
            uint32_t bfr[4][4];
            #pragma unroll
            for (int g2 = 0; g2 < 4; ++g2)
                LDSM4T(bfr[g2], sb + kk * 16 * (BPADH * 2) + g2 * 16 * 2);
            #pragma unroll
            for (int mf = 0; mf < 2; ++mf)
                #pragma unroll
                for (int nf = 0; nf < 8; ++nf) {
                    uint32_t bb[2] = { bfr[nf >> 1][(nf & 1) * 2],
                                       bfr[nf >> 1][(nf & 1) * 2 + 1] };
                    MMA16816(acc[mf][nf], af[mf], bb);
                }
        }
    }

    // epilogue: add bias, store fp32
    const int row0 = gm * TM + wm * 32 + (lane >> 2);
    const int col0 = gn * TN + wn * 64 + (lane & 3) * 2;
    #pragma unroll
    for (int mf = 0; mf < 2; ++mf) {
        #pragma unroll
        for (int nf = 0; nf < 8; ++nf) {
            const int r = row0 + mf * 16;
            const int c = col0 + nf * 8;
            const float b0 = __ldg(bias + c);
            const float b1 = __ldg(bias + c + 1);
            float2 v0 = make_float2(acc[mf][nf][0] + b0, acc[mf][nf][1] + b1);
            float2 v1 = make_float2(acc[mf][nf][2] + b0, acc[mf][nf][3] + b1);
            *(float2*)(out + (size_t)r * NN + c) = v0;
            *(float2*)(out + (size_t)(r + 8) * NN + c) = v1;
        }
    }
}

// ================= launch =================
extern "C" void kernel_launch(void* const* d_in, const int* in_sizes, int n_in,
                              void* d_out, int out_size)
{
    const float* x          = (const float*)d_in[0];  // (B, 1024)
    const float* perm_logit = (const float*)d_in[1];  // (DEPTH, 3)
    const float* abcd       = (const float*)d_in[2];  // (DEPTH, 4092, 2)
    const float* bias       = (const float*)d_in[3];  // (1024,)
    float* out = (float*)d_out;

    int Bn = in_sizes[0] / NN;
    int depth = in_sizes[1] / 3;

    static bool attr_set = false;
    if (!attr_set) {
        cudaFuncSetAttribute(gemm_kernel, cudaFuncAttributeMaxDynamicSharedMemorySize, SMEM_GEMM);
        attr_set = true;
    }

    // 1) M from butterfly on identity -> fp16 [k][n] (depth-0 perm chain sparse)
    butterfly_ident_kernel<<<NN, BT>>>(perm_logit, abcd, depth);
    // 2) HMMA GEMM with fused fp32->fp16 A conversion, single pass
    gemm_kernel<<<dim3(NN / TN, Bn / TM), 256, SMEM_GEMM>>>(x, bias, out);
}